// round 4
// baseline (speedup 1.0000x reference)
#include <cuda_runtime.h>

// ContextAwareTracker: LSTM encoder(50) + decoder(12), B=16384, H=128, I=5.
// Round 3->4: k-paired layout + fma.rn.f32x2 (FFMA2) to halve FMA issue slots.
// h, x, and packed weights store (k_even, k_odd) adjacent so ld.shared.v2.u64
// delivers .b64 operand pairs with no packing MOVs. Bias folded into the last
// k-pair via a constant 1.0 input lane.

#define BDIM 256
#define BB   128          // batch rows per CTA
#define NCTA 128          // 16384 / 128
#define NCH  16           // gate chunks per step (8 hidden units each)
#define NKP  67           // k-pairs: 64 (h) + 3 (x0..x4, 1.0-bias lane)
#define CHUNK_USED   (NKP * 64)   // 4288 floats per chunk
#define CHUNK_FLOATS 4352         // padded
#define CHUNK_F4     1072         // 4288/4

typedef unsigned long long u64;

__device__ float g_wpack[2 * NCH * CHUNK_FLOATS];

// Paired pack: chunk layout [kk][c][lane], k = 2*kk + lane.
//   k < 128   : Whh^T   (recurrent)
//   128..132  : Wih^T   (input, 5)
//   k == 133  : bih+bhh (multiplied by constant 1.0 lane of xT)
// column c = gate*8 + uu, global gate row j = gate*128 + ch*8 + uu.
__global__ void prep_kernel(const float* __restrict__ eWih, const float* __restrict__ eWhh,
                            const float* __restrict__ ebih, const float* __restrict__ ebhh,
                            const float* __restrict__ dWih, const float* __restrict__ dWhh,
                            const float* __restrict__ dbih, const float* __restrict__ dbhh)
{
    int idx = blockIdx.x * blockDim.x + threadIdx.x;
    const int total = 2 * NCH * CHUNK_USED;
    if (idx >= total) return;
    int net = idx / (NCH * CHUNK_USED);
    int rem = idx % (NCH * CHUNK_USED);
    int ch  = rem / CHUNK_USED;
    int pos = rem % CHUNK_USED;
    int kk   = pos >> 6;        // 0..66
    int cl   = pos & 63;
    int c    = cl >> 1;         // 0..31
    int lane = cl & 1;
    int k    = 2 * kk + lane;   // 0..133
    int gate = c >> 3, uu = c & 7;
    int j = gate * 128 + ch * 8 + uu;
    const float* Wih = net ? dWih : eWih;
    const float* Whh = net ? dWhh : eWhh;
    const float* bih = net ? dbih : ebih;
    const float* bhh = net ? dbhh : ebhh;
    float v;
    if (k < 128)      v = Whh[j * 128 + k];
    else if (k < 133) v = Wih[j * 5 + (k - 128)];
    else              v = bih[j] + bhh[j];
    g_wpack[(net * NCH + ch) * CHUNK_FLOATS + pos] = v;
}

__device__ __forceinline__ float sigf(float x) {
    return __fdividef(1.f, 1.f + __expf(-x));
}
__device__ __forceinline__ float tanh_(float x) {
    return fmaf(2.f, sigf(2.f * x), -1.f);
}

__device__ __forceinline__ void ffma2(u64& acc, u64 a, u64 b) {
    asm("fma.rn.f32x2 %0, %1, %2, %0;" : "+l"(acc) : "l"(a), "l"(b));
}
__device__ __forceinline__ float pair_sum(u64 p) {
    return __uint_as_float((unsigned)(p & 0xffffffffull)) +
           __uint_as_float((unsigned)(p >> 32));
}

__global__ __launch_bounds__(BDIM, 1)
void lstm_kernel(const float* __restrict__ x,
                 const float* __restrict__ linW,
                 const float* __restrict__ linb,
                 float* __restrict__ out)
{
    extern __shared__ float sm[];
    // h stored k-paired: h2[kk*256 + r*2 + (k&1)], kk = k>>1
    float* hbuf0 = sm;                    // 64*256 = 16384
    float* hbuf1 = hbuf0 + 128 * 128;
    float* wall  = hbuf1 + 128 * 128;     // staged weight chunk (paired layout)
    float* gsh   = wall + CHUNK_FLOATS;   // [32][132] gates chunk
    float* xT2   = gsh + 32 * 132;        // 3 kpairs * 256: x0..x4 + 1.0 lane

    const int tid = threadIdx.x;
    const int rb  = blockIdx.x * BB;

    const int tr = tid >> 3;   // 0..31 -> rows tr*4..+3
    const int tc = tid & 7;    // 0..7  -> cols tc*4..+3
    const int r0 = tr * 4;
    const int c0 = tc * 4;

    for (int i = tid; i < 128 * 128; i += BDIM) hbuf0[i] = 0.f;

    float c_loc[64];
    #pragma unroll
    for (int i = 0; i < 64; i++) c_loc[i] = 0.f;

    // initial weight prefetch (enc, chunk 0)
    float4 pf[5];
    {
        const float4* src = (const float4*)g_wpack;
        #pragma unroll
        for (int j = 0; j < 5; j++) {
            int i4 = tid + j * BDIM;
            if (i4 < CHUNK_F4) pf[j] = src[i4];
        }
    }
    __syncthreads();

    float* hc = hbuf0;
    float* hn = hbuf1;

    for (int t = 0; t < 62; t++) {
        const int net = (t < 50) ? 0 : 1;

        // stage encoder inputs (paired layout, bias lane = 1.0)
        if (t < 50 && tid < 128) {
            const float* xp = x + (size_t)(rb + tid) * 250 + t * 5;
            float x0 = xp[0], x1 = xp[1], x2 = xp[2], x3 = xp[3], x4 = xp[4];
            xT2[0 * 256 + tid * 2 + 0] = x0;
            xT2[0 * 256 + tid * 2 + 1] = x1;
            xT2[1 * 256 + tid * 2 + 0] = x2;
            xT2[1 * 256 + tid * 2 + 1] = x3;
            xT2[2 * 256 + tid * 2 + 0] = x4;
            xT2[2 * 256 + tid * 2 + 1] = 1.0f;
        }

        for (int ch = 0; ch < NCH; ch++) {
            // commit prefetched chunk to smem
            {
                float4* dst = (float4*)wall;
                #pragma unroll
                for (int j = 0; j < 5; j++) {
                    int i4 = tid + j * BDIM;
                    if (i4 < CHUNK_F4) dst[i4] = pf[j];
                }
            }
            __syncthreads();

            // prefetch next chunk (overlaps GEMM)
            {
                int nnet = (ch < NCH - 1) ? net : (((t + 1) < 50) ? 0 : 1);
                int nch  = (ch < NCH - 1) ? ch + 1 : 0;
                const float4* src =
                    (const float4*)(g_wpack + (size_t)(nnet * NCH + nch) * CHUNK_FLOATS);
                #pragma unroll
                for (int j = 0; j < 5; j++) {
                    int i4 = tid + j * BDIM;
                    if (i4 < CHUNK_F4) pf[j] = src[i4];
                }
            }

            // ---- GEMM: 128 rows x 32 cols, k paired (FFMA2) ----
            u64 acc[4][4];
            #pragma unroll
            for (int ri = 0; ri < 4; ri++)
                #pragma unroll
                for (int ci = 0; ci < 4; ci++) acc[ri][ci] = 0ull;

            const float* hp = hc + r0 * 2;
            const float* wp = wall + c0 * 2;
            #pragma unroll 8
            for (int kk = 0; kk < 64; kk++) {
                ulonglong2 h01 = *(const ulonglong2*)(hp + kk * 256);
                ulonglong2 h23 = *(const ulonglong2*)(hp + kk * 256 + 4);
                ulonglong2 w01 = *(const ulonglong2*)(wp + kk * 64);
                ulonglong2 w23 = *(const ulonglong2*)(wp + kk * 64 + 4);
                u64 hv[4] = {h01.x, h01.y, h23.x, h23.y};
                u64 wv[4] = {w01.x, w01.y, w23.x, w23.y};
                #pragma unroll
                for (int ri = 0; ri < 4; ri++)
                    #pragma unroll
                    for (int ci = 0; ci < 4; ci++)
                        ffma2(acc[ri][ci], hv[ri], wv[ci]);
            }
            #pragma unroll
            for (int kk = 0; kk < 3; kk++) {
                ulonglong2 h01 = *(const ulonglong2*)(xT2 + kk * 256 + r0 * 2);
                ulonglong2 h23 = *(const ulonglong2*)(xT2 + kk * 256 + r0 * 2 + 4);
                ulonglong2 w01 = *(const ulonglong2*)(wall + (64 + kk) * 64 + c0 * 2);
                ulonglong2 w23 = *(const ulonglong2*)(wall + (64 + kk) * 64 + c0 * 2 + 4);
                u64 hv[4] = {h01.x, h01.y, h23.x, h23.y};
                u64 wv[4] = {w01.x, w01.y, w23.x, w23.y};
                #pragma unroll
                for (int ri = 0; ri < 4; ri++)
                    #pragma unroll
                    for (int ci = 0; ci < 4; ci++)
                        ffma2(acc[ri][ci], hv[ri], wv[ci]);
            }

            // combine lanes, gates -> smem (gsh[c][r], row stride 132)
            #pragma unroll
            for (int ci = 0; ci < 4; ci++) {
                *(float4*)(gsh + (c0 + ci) * 132 + r0) =
                    make_float4(pair_sum(acc[0][ci]), pair_sum(acc[1][ci]),
                                pair_sum(acc[2][ci]), pair_sum(acc[3][ci]));
            }
            __syncthreads();

            // ---- elementwise: 128 rows x 8 units ----
            #pragma unroll
            for (int it = 0; it < 4; it++) {
                int idx = it * BDIM + tid;
                int r   = idx & 127;
                int uu  = idx >> 7;          // 0..7
                float iv = sigf (gsh[(     uu) * 132 + r]);
                float fv = sigf (gsh[( 8 + uu) * 132 + r]);
                float gv = tanh_(gsh[(16 + uu) * 132 + r]);
                float ov = sigf (gsh[(24 + uu) * 132 + r]);
                float cn = fmaf(fv, c_loc[ch * 4 + it], iv * gv);
                c_loc[ch * 4 + it] = cn;
                int u = ch * 8 + uu;
                hn[(u >> 1) * 256 + r * 2 + (u & 1)] = ov * tanh_(cn);
            }
        }
        __syncthreads();

        if (net == 1) {
            // pred = h_new @ lin_W^T + lin_b ; write out and feed back into xT
            int dt = t - 50;
            int r  = tid & 127;
            int j  = tid >> 7;               // 0..1
            float acc = linb[j];
            const float* lw = linW + j * 128;
            #pragma unroll 8
            for (int u = 0; u < 128; u++)
                acc = fmaf(hn[(u >> 1) * 256 + r * 2 + (u & 1)], lw[u], acc);
            out[((size_t)(rb + r) * 12 + dt) * 2 + j] = acc;
            xT2[0 * 256 + r * 2 + j] = acc;  // next dec_in; static stays in xT2
        }

        float* tmp = hc; hc = hn; hn = tmp;
    }
}

extern "C" void kernel_launch(void* const* d_in, const int* in_sizes, int n_in,
                              void* d_out, int out_size)
{
    const float* x    = (const float*)d_in[0];
    const float* eWih = (const float*)d_in[1];
    const float* eWhh = (const float*)d_in[2];
    const float* ebih = (const float*)d_in[3];
    const float* ebhh = (const float*)d_in[4];
    const float* dWih = (const float*)d_in[5];
    const float* dWhh = (const float*)d_in[6];
    const float* dbih = (const float*)d_in[7];
    const float* dbhh = (const float*)d_in[8];
    const float* lW   = (const float*)d_in[9];
    const float* lb   = (const float*)d_in[10];
    float* out = (float*)d_out;

    const int smem_bytes = (2 * 128 * 128 + CHUNK_FLOATS + 32 * 132 + 3 * 256) * 4;
    cudaFuncSetAttribute(lstm_kernel, cudaFuncAttributeMaxDynamicSharedMemorySize, smem_bytes);

    const int prep_total = 2 * NCH * CHUNK_USED;
    prep_kernel<<<(prep_total + 255) / 256, 256>>>(eWih, eWhh, ebih, ebhh,
                                                   dWih, dWhh, dbih, dbhh);
    lstm_kernel<<<NCTA, BDIM, smem_bytes>>>(x, lW, lb, out);
}

// round 6
// speedup vs baseline: 2.9403x; 2.9403x over previous
#include <cuda_runtime.h>
#include <cuda_bf16.h>
#include <stdint.h>

// ContextAwareTracker: LSTM enc(50)+dec(12), B=16384, H=128, I=5.
// Round 6: base-ISA tensor cores (mma.sync m16n8k16 bf16, f32 accum) with
// 3-term hi/lo bf16 split precision. Persistent h (smem, ping-pong hi/lo) and
// c (regs/local) per CTA across all 62 steps. Weights pre-packed [gatecol][k]
// and streamed via cp.async double buffer. Gate cols interleaved c=4u+g.
// NOTE: tcgen05 is NOT available (harness PTX target is sm_103 base).

#define BDIM 256
#define KP   152          // A (h|x|bias) k-pad: 304B row stride, ldmatrix conflict-free
#define ROWB 304
#define KW   144          // W k-pad: 288B row stride
#define WROWB 288
#define ABUF 38912        // 128 * 304
#define WBLK 36864        // 128 * 288
#define SM_W (4 * ABUF)   // A: [buf(2)][split(2)][128][KP]
#define SMEM_TOTAL (SM_W + 2 * WBLK)   // 229376
#define NBLOCKS 496       // 62 steps * 8 (4 chunks x {Wh,Wl})

__device__ __nv_bfloat16 g_wpack[16 * 128 * KW];  // [net(2)][chunk(4)][split(2)][n 128][k 144]

// gate col interleave: C = 4*unit + gate (gate: 0=i,1=f,2=g,3=o)
__global__ void prep_kernel(const float* __restrict__ eWih, const float* __restrict__ eWhh,
                            const float* __restrict__ ebih, const float* __restrict__ ebhh,
                            const float* __restrict__ dWih, const float* __restrict__ dWhh,
                            const float* __restrict__ dbih, const float* __restrict__ dbhh)
{
    int idx = blockIdx.x * blockDim.x + threadIdx.x;
    if (idx >= 16 * 128 * KW) return;
    int block = idx / (128 * KW);
    int e     = idx % (128 * KW);
    int n = e / KW, k = e % KW;
    int net = block >> 3, i8 = block & 7;
    int chunk = i8 >> 1, split = i8 & 1;
    int C = chunk * 128 + n;
    int u = C >> 2, g = C & 3;
    int j = g * 128 + u;
    const float* Wih = net ? dWih : eWih;
    const float* Whh = net ? dWhh : eWhh;
    const float* bih = net ? dbih : ebih;
    const float* bhh = net ? dbhh : ebhh;
    float w = 0.f;
    if (k < 128)       w = Whh[j * 128 + k];
    else if (k < 133)  w = Wih[j * 5 + (k - 128)];
    else if (k == 133) w = bih[j] + bhh[j];      // bias lane (A has 1.0 at k=133)
    __nv_bfloat16 hi = __float2bfloat16_rn(w);
    __nv_bfloat16 v  = split ? __float2bfloat16_rn(w - __bfloat162float(hi)) : hi;
    g_wpack[(size_t)block * (128 * KW) + e] = v;
}

__device__ __forceinline__ uint32_t smem_u32(const void* p) {
    uint32_t a;
    asm("{ .reg .u64 t; cvta.to.shared.u64 t, %1; cvt.u32.u64 %0, t; }" : "=r"(a) : "l"(p));
    return a;
}
__device__ __forceinline__ float sigf(float v)   { return __fdividef(1.f, 1.f + __expf(-v)); }
__device__ __forceinline__ float tanhf_(float v) { return fmaf(2.f, sigf(2.f * v), -1.f); }
__device__ __forceinline__ unsigned short bfu(float v) {
    return __bfloat16_as_ushort(__float2bfloat16_rn(v));
}
__device__ __forceinline__ float ubf(unsigned short u) {
    return __bfloat162float(__ushort_as_bfloat16(u));
}

#define LDSX4(r, addr) \
    asm volatile("ldmatrix.sync.aligned.m8n8.x4.shared.b16 {%0,%1,%2,%3}, [%4];" \
        : "=r"((r)[0]), "=r"((r)[1]), "=r"((r)[2]), "=r"((r)[3]) : "r"(addr) : "memory")

#define MMA16816(d, a, b0, b1) \
    asm volatile("mma.sync.aligned.m16n8k16.row.col.f32.bf16.bf16.f32 " \
        "{%0,%1,%2,%3},{%4,%5,%6,%7},{%8,%9},{%0,%1,%2,%3};" \
        : "+f"((d)[0]), "+f"((d)[1]), "+f"((d)[2]), "+f"((d)[3]) \
        : "r"((a)[0]), "r"((a)[1]), "r"((a)[2]), "r"((a)[3]), "r"(b0), "r"(b1))

__device__ __forceinline__ void cp_block(int lin, uint32_t dst, int tid) {
    int gblock = ((lin >= 400) ? 8 : 0) + (lin & 7);
    const char* src = (const char*)g_wpack + (size_t)gblock * WBLK + tid * 16;
    uint32_t d = dst + tid * 16;
    #pragma unroll
    for (int i = 0; i < 9; i++) {   // 2304 x 16B = 9 * 256 threads
        asm volatile("cp.async.ca.shared.global [%0], [%1], 16;"
                     :: "r"(d + i * 4096), "l"(src + i * 4096) : "memory");
    }
}

__global__ void __launch_bounds__(BDIM, 1)
lstm_mma(const float* __restrict__ x,
         const float* __restrict__ linW,
         const float* __restrict__ linb,
         float* __restrict__ out)
{
    extern __shared__ char smem[];
    const uint32_t sb = smem_u32(smem);
    const int tid  = threadIdx.x;
    const int lane = tid & 31;
    const int w    = tid >> 5;
    const int m0   = (w & 1) * 64;   // warp's row half
    const int nq   = w >> 1;         // warp's 32-col quarter within chunk
    const int base_row = blockIdx.x * 128;

    // zero all smem (h=0, x pad lanes=0)
    {
        uint4 z = make_uint4(0, 0, 0, 0);
        uint4* p = (uint4*)smem;
        for (int i = tid; i < SMEM_TOTAL / 16; i += BDIM) p[i] = z;
    }
    __syncthreads();
    if (tid < 128) {    // bias lane k=133 = 1.0 (hi) in both buffers
        *(unsigned short*)(smem + 0 * ABUF + tid * ROWB + 266) = 0x3F80;
        *(unsigned short*)(smem + 2 * ABUF + tid * ROWB + 266) = 0x3F80;
    }

    float c_loc[64];
    #pragma unroll
    for (int i = 0; i < 64; i++) c_loc[i] = 0.f;

    cp_block(0, sb + SM_W, tid);
    asm volatile("cp.async.commit_group;" ::: "memory");
    __syncthreads();

    int cur = 0;
    for (int t = 0; t < 62; t++) {
        const int nb = cur ^ 1;

        // stage x(t) into k=128..132 of current buffer (t==49: both buffers,
        // providing ctx + last_velocity for the decoder's dec_in0)
        if (t < 50 && tid < 128) {
            const float* xp = x + (size_t)(base_row + tid) * 250 + (size_t)t * 5;
            float v[5] = { xp[0], xp[1], xp[2], xp[3], xp[4] };
            #pragma unroll
            for (int b = 0; b < 2; b++) {
                if (b == 1 && t != 49) break;
                int bsel = b == 0 ? cur : nb;
                char* bh = smem + bsel * 2 * ABUF + tid * ROWB + 256;  // k=128
                #pragma unroll
                for (int i = 0; i < 5; i++) {
                    unsigned short hu = bfu(v[i]);
                    *(unsigned short*)(bh + i * 2) = hu;
                    *(unsigned short*)(bh + ABUF + i * 2) = bfu(v[i] - ubf(hu));
                }
            }
        }

        float acc[4][4][4];
        for (int c8 = 0; c8 < 8; c8++) {
            const int lin = t * 8 + c8;
            int nl = lin + 1; if (nl > NBLOCKS - 1) nl = NBLOCKS - 1;
            cp_block(nl, sb + SM_W + (uint32_t)(nl & 1) * WBLK, tid);
            asm volatile("cp.async.commit_group;" ::: "memory");
            asm volatile("cp.async.wait_group 1;" ::: "memory");
            __syncthreads();

            const uint32_t wb = sb + SM_W + (uint32_t)(lin & 1) * WBLK;
            const uint32_t ab = sb + (uint32_t)cur * 2 * ABUF;
            const int chunk = c8 >> 1;

            if ((c8 & 1) == 0) {
                // ---- Wh phase: acc = Ah*Wh + Al*Wh ----
                #pragma unroll
                for (int mt = 0; mt < 4; mt++)
                    #pragma unroll
                    for (int nt = 0; nt < 4; nt++)
                        #pragma unroll
                        for (int q = 0; q < 4; q++) acc[mt][nt][q] = 0.f;
                #pragma unroll
                for (int kt = 0; kt < 9; kt++) {
                    uint32_t ah[4][4], al[4][4], bb[2][4];
                    const uint32_t kof = (uint32_t)((kt * 16 + ((lane >> 4) << 3)) << 1);
                    #pragma unroll
                    for (int mt = 0; mt < 4; mt++) {
                        uint32_t ra = ab + (uint32_t)(m0 + mt * 16 + (lane & 15)) * ROWB + kof;
                        LDSX4(ah[mt], ra);
                        LDSX4(al[mt], ra + ABUF);
                    }
                    #pragma unroll
                    for (int p = 0; p < 2; p++) {
                        uint32_t rb = wb + (uint32_t)(nq * 32 + p * 16 + ((lane >> 4) << 3)
                                      + (lane & 7)) * WROWB
                                      + (uint32_t)((kt * 16 + (lane & 8)) << 1);
                        LDSX4(bb[p], rb);
                    }
                    #pragma unroll
                    for (int mt = 0; mt < 4; mt++)
                        #pragma unroll
                        for (int nt = 0; nt < 4; nt++) {
                            uint32_t b0 = bb[nt >> 1][(nt & 1) * 2];
                            uint32_t b1 = bb[nt >> 1][(nt & 1) * 2 + 1];
                            MMA16816(acc[mt][nt], ah[mt], b0, b1);
                            MMA16816(acc[mt][nt], al[mt], b0, b1);
                        }
                }
            } else {
                // ---- Wl phase: acc += Ah*Wl, then epilogue ----
                #pragma unroll
                for (int kt = 0; kt < 9; kt++) {
                    uint32_t ah[4][4], bb[2][4];
                    const uint32_t kof = (uint32_t)((kt * 16 + ((lane >> 4) << 3)) << 1);
                    #pragma unroll
                    for (int mt = 0; mt < 4; mt++) {
                        uint32_t ra = ab + (uint32_t)(m0 + mt * 16 + (lane & 15)) * ROWB + kof;
                        LDSX4(ah[mt], ra);
                    }
                    #pragma unroll
                    for (int p = 0; p < 2; p++) {
                        uint32_t rb = wb + (uint32_t)(nq * 32 + p * 16 + ((lane >> 4) << 3)
                                      + (lane & 7)) * WROWB
                                      + (uint32_t)((kt * 16 + (lane & 8)) << 1);
                        LDSX4(bb[p], rb);
                    }
                    #pragma unroll
                    for (int mt = 0; mt < 4; mt++)
                        #pragma unroll
                        for (int nt = 0; nt < 4; nt++)
                            MMA16816(acc[mt][nt], ah[mt],
                                     bb[nt >> 1][(nt & 1) * 2], bb[nt >> 1][(nt & 1) * 2 + 1]);
                }

                // epilogue: each thread owns one (row, unit) cell per tile
                const int cb_u = chunk * 32 + nq * 8;
                const bool even = !(lane & 1);
                #pragma unroll
                for (int mt = 0; mt < 4; mt++) {
                    #pragma unroll
                    for (int nt = 0; nt < 4; nt++) {
                        float c0 = acc[mt][nt][0], c1 = acc[mt][nt][1];
                        float c2 = acc[mt][nt][2], c3 = acc[mt][nt][3];
                        float x0 = __shfl_xor_sync(0xffffffffu, c0, 1);
                        float x1 = __shfl_xor_sync(0xffffffffu, c1, 1);
                        float x2 = __shfl_xor_sync(0xffffffffu, c2, 1);
                        float x3 = __shfl_xor_sync(0xffffffffu, c3, 1);
                        float iv = even ? c0 : x2;
                        float fv = even ? c1 : x3;
                        float gv = even ? x0 : c2;
                        float ov = even ? x1 : c3;
                        int row = m0 + mt * 16 + (lane >> 2) + (even ? 0 : 8);
                        int ug  = cb_u + nt * 2 + ((lane & 3) >> 1);
                        int ci  = chunk * 16 + mt * 4 + nt;
                        float ivs = sigf(iv), fvs = sigf(fv);
                        float gvt = tanhf_(gv), ovs = sigf(ov);
                        float cn = fmaf(fvs, c_loc[ci], ivs * gvt);
                        c_loc[ci] = cn;
                        float hv = ovs * tanhf_(cn);
                        unsigned short hu = bfu(hv);
                        char* bh = smem + nb * 2 * ABUF + row * ROWB + ug * 2;
                        *(unsigned short*)bh = hu;
                        *(unsigned short*)(bh + ABUF) = bfu(hv - ubf(hu));
                    }
                }
            }
            __syncthreads();
        }

        if (t >= 50) {   // pred = h_new @ linW^T + linb; feed back velocity
            int r = tid & 127, jj = tid >> 7;
            const char* bh = smem + nb * 2 * ABUF + r * ROWB;
            float accp = __ldg(linb + jj);
            const float* lw = linW + jj * 128;
            #pragma unroll 16
            for (int u = 0; u < 128; u++) {
                float hv = ubf(*(const unsigned short*)(bh + u * 2))
                         + ubf(*(const unsigned short*)(bh + ABUF + u * 2));
                accp = fmaf(hv, __ldg(lw + u), accp);
            }
            out[((size_t)(base_row + r) * 12 + (t - 50)) * 2 + jj] = accp;
            unsigned short hu = bfu(accp);
            char* bx = smem + nb * 2 * ABUF + r * ROWB + (128 + jj) * 2;
            *(unsigned short*)bx = hu;
            *(unsigned short*)(bx + ABUF) = bfu(accp - ubf(hu));
        }

        cur = nb;
    }
}

extern "C" void kernel_launch(void* const* d_in, const int* in_sizes, int n_in,
                              void* d_out, int out_size)
{
    const float* x    = (const float*)d_in[0];
    const float* eWih = (const float*)d_in[1];
    const float* eWhh = (const float*)d_in[2];
    const float* ebih = (const float*)d_in[3];
    const float* ebhh = (const float*)d_in[4];
    const float* dWih = (const float*)d_in[5];
    const float* dWhh = (const float*)d_in[6];
    const float* dbih = (const float*)d_in[7];
    const float* dbhh = (const float*)d_in[8];
    const float* lW   = (const float*)d_in[9];
    const float* lb   = (const float*)d_in[10];
    float* out = (float*)d_out;

    cudaFuncSetAttribute(lstm_mma, cudaFuncAttributeMaxDynamicSharedMemorySize, SMEM_TOTAL);

    const int prep_total = 16 * 128 * KW;
    prep_kernel<<<(prep_total + 255) / 256, 256>>>(eWih, eWhh, ebih, ebhh,
                                                   dWih, dWhh, dbih, dbhh);
    lstm_mma<<<128, BDIM, SMEM_TOTAL>>>(x, lW, lb, out);
}

// round 7
// speedup vs baseline: 2.9483x; 1.0027x over previous
#include <cuda_runtime.h>
#include <cuda_bf16.h>
#include <stdint.h>

// ContextAwareTracker: LSTM enc(50)+dec(12), B=16384, H=128, I=5.
// Round 6: base-ISA tensor cores (mma.sync m16n8k16 bf16, f32 accum) with
// 3-term hi/lo bf16 split precision. Persistent h (smem, ping-pong hi/lo) and
// c (regs/local) per CTA across all 62 steps. Weights pre-packed [gatecol][k]
// and streamed via cp.async double buffer. Gate cols interleaved c=4u+g.
// NOTE: tcgen05 is NOT available (harness PTX target is sm_103 base).

#define BDIM 256
#define KP   152          // A (h|x|bias) k-pad: 304B row stride, ldmatrix conflict-free
#define ROWB 304
#define KW   144          // W k-pad: 288B row stride
#define WROWB 288
#define ABUF 38912        // 128 * 304
#define WBLK 36864        // 128 * 288
#define SM_W (4 * ABUF)   // A: [buf(2)][split(2)][128][KP]
#define SMEM_TOTAL (SM_W + 2 * WBLK)   // 229376
#define NBLOCKS 496       // 62 steps * 8 (4 chunks x {Wh,Wl})

__device__ __nv_bfloat16 g_wpack[16 * 128 * KW];  // [net(2)][chunk(4)][split(2)][n 128][k 144]

// gate col interleave: C = 4*unit + gate (gate: 0=i,1=f,2=g,3=o)
__global__ void prep_kernel(const float* __restrict__ eWih, const float* __restrict__ eWhh,
                            const float* __restrict__ ebih, const float* __restrict__ ebhh,
                            const float* __restrict__ dWih, const float* __restrict__ dWhh,
                            const float* __restrict__ dbih, const float* __restrict__ dbhh)
{
    int idx = blockIdx.x * blockDim.x + threadIdx.x;
    if (idx >= 16 * 128 * KW) return;
    int block = idx / (128 * KW);
    int e     = idx % (128 * KW);
    int n = e / KW, k = e % KW;
    int net = block >> 3, i8 = block & 7;
    int chunk = i8 >> 1, split = i8 & 1;
    int C = chunk * 128 + n;
    int u = C >> 2, g = C & 3;
    int j = g * 128 + u;
    const float* Wih = net ? dWih : eWih;
    const float* Whh = net ? dWhh : eWhh;
    const float* bih = net ? dbih : ebih;
    const float* bhh = net ? dbhh : ebhh;
    float w = 0.f;
    if (k < 128)       w = Whh[j * 128 + k];
    else if (k < 133)  w = Wih[j * 5 + (k - 128)];
    else if (k == 133) w = bih[j] + bhh[j];      // bias lane (A has 1.0 at k=133)
    __nv_bfloat16 hi = __float2bfloat16_rn(w);
    __nv_bfloat16 v  = split ? __float2bfloat16_rn(w - __bfloat162float(hi)) : hi;
    g_wpack[(size_t)block * (128 * KW) + e] = v;
}

__device__ __forceinline__ uint32_t smem_u32(const void* p) {
    uint32_t a;
    asm("{ .reg .u64 t; cvta.to.shared.u64 t, %1; cvt.u32.u64 %0, t; }" : "=r"(a) : "l"(p));
    return a;
}
__device__ __forceinline__ float sigf(float v)   { return __fdividef(1.f, 1.f + __expf(-v)); }
__device__ __forceinline__ float tanhf_(float v) { return fmaf(2.f, sigf(2.f * v), -1.f); }
__device__ __forceinline__ unsigned short bfu(float v) {
    return __bfloat16_as_ushort(__float2bfloat16_rn(v));
}
__device__ __forceinline__ float ubf(unsigned short u) {
    return __bfloat162float(__ushort_as_bfloat16(u));
}

#define LDSX4(r, addr) \
    asm volatile("ldmatrix.sync.aligned.m8n8.x4.shared.b16 {%0,%1,%2,%3}, [%4];" \
        : "=r"((r)[0]), "=r"((r)[1]), "=r"((r)[2]), "=r"((r)[3]) : "r"(addr) : "memory")

#define MMA16816(d, a, b0, b1) \
    asm volatile("mma.sync.aligned.m16n8k16.row.col.f32.bf16.bf16.f32 " \
        "{%0,%1,%2,%3},{%4,%5,%6,%7},{%8,%9},{%0,%1,%2,%3};" \
        : "+f"((d)[0]), "+f"((d)[1]), "+f"((d)[2]), "+f"((d)[3]) \
        : "r"((a)[0]), "r"((a)[1]), "r"((a)[2]), "r"((a)[3]), "r"(b0), "r"(b1))

__device__ __forceinline__ void cp_block(int lin, uint32_t dst, int tid) {
    int gblock = ((lin >= 400) ? 8 : 0) + (lin & 7);
    const char* src = (const char*)g_wpack + (size_t)gblock * WBLK + tid * 16;
    uint32_t d = dst + tid * 16;
    #pragma unroll
    for (int i = 0; i < 9; i++) {   // 2304 x 16B = 9 * 256 threads
        asm volatile("cp.async.ca.shared.global [%0], [%1], 16;"
                     :: "r"(d + i * 4096), "l"(src + i * 4096) : "memory");
    }
}

__global__ void __launch_bounds__(BDIM, 1)
lstm_mma(const float* __restrict__ x,
         const float* __restrict__ linW,
         const float* __restrict__ linb,
         float* __restrict__ out)
{
    extern __shared__ char smem[];
    const uint32_t sb = smem_u32(smem);
    const int tid  = threadIdx.x;
    const int lane = tid & 31;
    const int w    = tid >> 5;
    const int m0   = (w & 1) * 64;   // warp's row half
    const int nq   = w >> 1;         // warp's 32-col quarter within chunk
    const int base_row = blockIdx.x * 128;

    // zero all smem (h=0, x pad lanes=0)
    {
        uint4 z = make_uint4(0, 0, 0, 0);
        uint4* p = (uint4*)smem;
        for (int i = tid; i < SMEM_TOTAL / 16; i += BDIM) p[i] = z;
    }
    __syncthreads();
    if (tid < 128) {    // bias lane k=133 = 1.0 (hi) in both buffers
        *(unsigned short*)(smem + 0 * ABUF + tid * ROWB + 266) = 0x3F80;
        *(unsigned short*)(smem + 2 * ABUF + tid * ROWB + 266) = 0x3F80;
    }

    float c_loc[64];
    #pragma unroll
    for (int i = 0; i < 64; i++) c_loc[i] = 0.f;

    cp_block(0, sb + SM_W, tid);
    asm volatile("cp.async.commit_group;" ::: "memory");
    __syncthreads();

    int cur = 0;
    for (int t = 0; t < 62; t++) {
        const int nb = cur ^ 1;

        // stage x(t) into k=128..132 of current buffer (t==49: both buffers,
        // providing ctx + last_velocity for the decoder's dec_in0)
        if (t < 50 && tid < 128) {
            const float* xp = x + (size_t)(base_row + tid) * 250 + (size_t)t * 5;
            float v[5] = { xp[0], xp[1], xp[2], xp[3], xp[4] };
            #pragma unroll
            for (int b = 0; b < 2; b++) {
                if (b == 1 && t != 49) break;
                int bsel = b == 0 ? cur : nb;
                char* bh = smem + bsel * 2 * ABUF + tid * ROWB + 256;  // k=128
                #pragma unroll
                for (int i = 0; i < 5; i++) {
                    unsigned short hu = bfu(v[i]);
                    *(unsigned short*)(bh + i * 2) = hu;
                    *(unsigned short*)(bh + ABUF + i * 2) = bfu(v[i] - ubf(hu));
                }
            }
        }

        float acc[4][4][4];
        for (int c8 = 0; c8 < 8; c8++) {
            const int lin = t * 8 + c8;
            int nl = lin + 1; if (nl > NBLOCKS - 1) nl = NBLOCKS - 1;
            cp_block(nl, sb + SM_W + (uint32_t)(nl & 1) * WBLK, tid);
            asm volatile("cp.async.commit_group;" ::: "memory");
            asm volatile("cp.async.wait_group 1;" ::: "memory");
            __syncthreads();

            const uint32_t wb = sb + SM_W + (uint32_t)(lin & 1) * WBLK;
            const uint32_t ab = sb + (uint32_t)cur * 2 * ABUF;
            const int chunk = c8 >> 1;

            if ((c8 & 1) == 0) {
                // ---- Wh phase: acc = Ah*Wh + Al*Wh ----
                #pragma unroll
                for (int mt = 0; mt < 4; mt++)
                    #pragma unroll
                    for (int nt = 0; nt < 4; nt++)
                        #pragma unroll
                        for (int q = 0; q < 4; q++) acc[mt][nt][q] = 0.f;
                #pragma unroll
                for (int kt = 0; kt < 9; kt++) {
                    uint32_t ah[4][4], al[4][4], bb[2][4];
                    const uint32_t kof = (uint32_t)((kt * 16 + ((lane >> 4) << 3)) << 1);
                    #pragma unroll
                    for (int mt = 0; mt < 4; mt++) {
                        uint32_t ra = ab + (uint32_t)(m0 + mt * 16 + (lane & 15)) * ROWB + kof;
                        LDSX4(ah[mt], ra);
                        LDSX4(al[mt], ra + ABUF);
                    }
                    #pragma unroll
                    for (int p = 0; p < 2; p++) {
                        uint32_t rb = wb + (uint32_t)(nq * 32 + p * 16 + ((lane >> 4) << 3)
                                      + (lane & 7)) * WROWB
                                      + (uint32_t)((kt * 16 + (lane & 8)) << 1);
                        LDSX4(bb[p], rb);
                    }
                    #pragma unroll
                    for (int mt = 0; mt < 4; mt++)
                        #pragma unroll
                        for (int nt = 0; nt < 4; nt++) {
                            uint32_t b0 = bb[nt >> 1][(nt & 1) * 2];
                            uint32_t b1 = bb[nt >> 1][(nt & 1) * 2 + 1];
                            MMA16816(acc[mt][nt], ah[mt], b0, b1);
                            MMA16816(acc[mt][nt], al[mt], b0, b1);
                        }
                }
            } else {
                // ---- Wl phase: acc += Ah*Wl, then epilogue ----
                #pragma unroll
                for (int kt = 0; kt < 9; kt++) {
                    uint32_t ah[4][4], bb[2][4];
                    const uint32_t kof = (uint32_t)((kt * 16 + ((lane >> 4) << 3)) << 1);
                    #pragma unroll
                    for (int mt = 0; mt < 4; mt++) {
                        uint32_t ra = ab + (uint32_t)(m0 + mt * 16 + (lane & 15)) * ROWB + kof;
                        LDSX4(ah[mt], ra);
                    }
                    #pragma unroll
                    for (int p = 0; p < 2; p++) {
                        uint32_t rb = wb + (uint32_t)(nq * 32 + p * 16 + ((lane >> 4) << 3)
                                      + (lane & 7)) * WROWB
                                      + (uint32_t)((kt * 16 + (lane & 8)) << 1);
                        LDSX4(bb[p], rb);
                    }
                    #pragma unroll
                    for (int mt = 0; mt < 4; mt++)
                        #pragma unroll
                        for (int nt = 0; nt < 4; nt++)
                            MMA16816(acc[mt][nt], ah[mt],
                                     bb[nt >> 1][(nt & 1) * 2], bb[nt >> 1][(nt & 1) * 2 + 1]);
                }

                // epilogue: each thread owns one (row, unit) cell per tile
                const int cb_u = chunk * 32 + nq * 8;
                const bool even = !(lane & 1);
                #pragma unroll
                for (int mt = 0; mt < 4; mt++) {
                    #pragma unroll
                    for (int nt = 0; nt < 4; nt++) {
                        float c0 = acc[mt][nt][0], c1 = acc[mt][nt][1];
                        float c2 = acc[mt][nt][2], c3 = acc[mt][nt][3];
                        float x0 = __shfl_xor_sync(0xffffffffu, c0, 1);
                        float x1 = __shfl_xor_sync(0xffffffffu, c1, 1);
                        float x2 = __shfl_xor_sync(0xffffffffu, c2, 1);
                        float x3 = __shfl_xor_sync(0xffffffffu, c3, 1);
                        float iv = even ? c0 : x2;
                        float fv = even ? c1 : x3;
                        float gv = even ? x0 : c2;
                        float ov = even ? x1 : c3;
                        int row = m0 + mt * 16 + (lane >> 2) + (even ? 0 : 8);
                        int ug  = cb_u + nt * 2 + ((lane & 3) >> 1);
                        int ci  = chunk * 16 + mt * 4 + nt;
                        float ivs = sigf(iv), fvs = sigf(fv);
                        float gvt = tanhf_(gv), ovs = sigf(ov);
                        float cn = fmaf(fvs, c_loc[ci], ivs * gvt);
                        c_loc[ci] = cn;
                        float hv = ovs * tanhf_(cn);
                        unsigned short hu = bfu(hv);
                        char* bh = smem + nb * 2 * ABUF + row * ROWB + ug * 2;
                        *(unsigned short*)bh = hu;
                        *(unsigned short*)(bh + ABUF) = bfu(hv - ubf(hu));
                    }
                }
            }
            __syncthreads();
        }

        if (t >= 50) {   // pred = h_new @ linW^T + linb; feed back velocity
            int r = tid & 127, jj = tid >> 7;
            const char* bh = smem + nb * 2 * ABUF + r * ROWB;
            float accp = __ldg(linb + jj);
            const float* lw = linW + jj * 128;
            #pragma unroll 16
            for (int u = 0; u < 128; u++) {
                float hv = ubf(*(const unsigned short*)(bh + u * 2))
                         + ubf(*(const unsigned short*)(bh + ABUF + u * 2));
                accp = fmaf(hv, __ldg(lw + u), accp);
            }
            out[((size_t)(base_row + r) * 12 + (t - 50)) * 2 + jj] = accp;
            unsigned short hu = bfu(accp);
            char* bx = smem + nb * 2 * ABUF + r * ROWB + (128 + jj) * 2;
            *(unsigned short*)bx = hu;
            *(unsigned short*)(bx + ABUF) = bfu(accp - ubf(hu));
        }

        cur = nb;
    }
}

extern "C" void kernel_launch(void* const* d_in, const int* in_sizes, int n_in,
                              void* d_out, int out_size)
{
    const float* x    = (const float*)d_in[0];
    const float* eWih = (const float*)d_in[1];
    const float* eWhh = (const float*)d_in[2];
    const float* ebih = (const float*)d_in[3];
    const float* ebhh = (const float*)d_in[4];
    const float* dWih = (const float*)d_in[5];
    const float* dWhh = (const float*)d_in[6];
    const float* dbih = (const float*)d_in[7];
    const float* dbhh = (const float*)d_in[8];
    const float* lW   = (const float*)d_in[9];
    const float* lb   = (const float*)d_in[10];
    float* out = (float*)d_out;

    cudaFuncSetAttribute(lstm_mma, cudaFuncAttributeMaxDynamicSharedMemorySize, SMEM_TOTAL);

    const int prep_total = 16 * 128 * KW;
    prep_kernel<<<(prep_total + 255) / 256, 256>>>(eWih, eWhh, ebih, ebhh,
                                                   dWih, dWhh, dbih, dbhh);
    lstm_mma<<<128, BDIM, SMEM_TOTAL>>>(x, lW, lb, out);
}

// round 8
// speedup vs baseline: 2.9804x; 1.0109x over previous
#include <cuda_runtime.h>
#include <cuda_bf16.h>
#include <stdint.h>

// ContextAwareTracker: LSTM enc(50)+dec(12), B=16384, H=128, I=5.
// Round 8: same 3-term hi/lo bf16 mma.sync math as R7, restructured:
//  - W streamed in 64-gate-col blocks with BOTH splits resident (fused 3-MMA)
//  - warp tile 32 rows x 32 cols -> acc = 32 regs (R7: 64, spilled at 255 cap)
//  - MMA issued in 3 sweeps over 8 independent tiles (dep distance 8)
//  - 1 barrier per chunk-iter (R7: 2): 9/step vs 16
// NOTE: tcgen05 unavailable (harness PTX target sm_103 base) - mma.sync only.

#define BDIM 256
#define KP   152          // A k-pad: 304B row stride (19x16B, odd -> conflict-free LDSM)
#define ROWB 304
#define KW   144          // W k-pad: 288B row stride
#define WROWB 288
#define ABUF 38912        // 128 * 304 (one split, one buffer)
#define SM_W (4 * ABUF)   // 155648; A: [buf 2][split 2][128][KP]
#define WBLK 36864        // 64 cols x 2 splits x 288B
#define SMEM_TOTAL (SM_W + 2 * WBLK)   // 229376 <= 232448
#define NBLOCKS 496       // 62 steps * 8 chunk-iters

__device__ __nv_bfloat16 g_wpack[16 * 18432];  // [net 2][chunk64 8][split 2][n 64][k 144]

// gate col interleave: C = 4*unit + gate (0=i,1=f,2=g,3=o)
__global__ void prep_kernel(const float* __restrict__ eWih, const float* __restrict__ eWhh,
                            const float* __restrict__ ebih, const float* __restrict__ ebhh,
                            const float* __restrict__ dWih, const float* __restrict__ dWhh,
                            const float* __restrict__ dbih, const float* __restrict__ dbhh)
{
    int idx = blockIdx.x * blockDim.x + threadIdx.x;
    if (idx >= 16 * 18432) return;
    int block = idx / 18432;
    int e     = idx % 18432;
    int split = e / 9216;
    int r     = (e % 9216) / 144;
    int k     = e % 144;
    int net = block >> 3, chunk = block & 7;
    int C = chunk * 64 + r;
    int u = C >> 2, g = C & 3;
    int j = g * 128 + u;
    const float* Wih = net ? dWih : eWih;
    const float* Whh = net ? dWhh : eWhh;
    const float* bih = net ? dbih : ebih;
    const float* bhh = net ? dbhh : ebhh;
    float w = 0.f;
    if (k < 128)       w = Whh[j * 128 + k];
    else if (k < 133)  w = Wih[j * 5 + (k - 128)];
    else if (k == 133) w = bih[j] + bhh[j];      // bias lane (A has 1.0 at k=133)
    __nv_bfloat16 hi = __float2bfloat16_rn(w);
    __nv_bfloat16 v  = split ? __float2bfloat16_rn(w - __bfloat162float(hi)) : hi;
    g_wpack[(size_t)block * 18432 + e] = v;
}

__device__ __forceinline__ uint32_t smem_u32(const void* p) {
    uint32_t a;
    asm("{ .reg .u64 t; cvta.to.shared.u64 t, %1; cvt.u32.u64 %0, t; }" : "=r"(a) : "l"(p));
    return a;
}
__device__ __forceinline__ float sigf(float v)   { return __fdividef(1.f, 1.f + __expf(-v)); }
__device__ __forceinline__ float tanhf_(float v) { return fmaf(2.f, sigf(2.f * v), -1.f); }
__device__ __forceinline__ unsigned short bfu(float v) {
    return __bfloat16_as_ushort(__float2bfloat16_rn(v));
}
__device__ __forceinline__ float ubf(unsigned short u) {
    return __bfloat162float(__ushort_as_bfloat16(u));
}

#define LDSX4(r, addr) \
    asm volatile("ldmatrix.sync.aligned.m8n8.x4.shared.b16 {%0,%1,%2,%3}, [%4];" \
        : "=r"((r)[0]), "=r"((r)[1]), "=r"((r)[2]), "=r"((r)[3]) : "r"(addr) : "memory")

#define MMA16816(d, a, b0, b1) \
    asm volatile("mma.sync.aligned.m16n8k16.row.col.f32.bf16.bf16.f32 " \
        "{%0,%1,%2,%3},{%4,%5,%6,%7},{%8,%9},{%0,%1,%2,%3};" \
        : "+f"((d)[0]), "+f"((d)[1]), "+f"((d)[2]), "+f"((d)[3]) \
        : "r"((a)[0]), "r"((a)[1]), "r"((a)[2]), "r"((a)[3]), "r"(b0), "r"(b1))

__device__ __forceinline__ void cp_block(int lin, uint32_t dst, int tid) {
    int gblock = ((lin >= 400) ? 8 : 0) + (lin & 7);
    const char* src = (const char*)g_wpack + (size_t)gblock * WBLK + tid * 16;
    uint32_t d = dst + tid * 16;
    #pragma unroll
    for (int i = 0; i < 9; i++) {   // 2304 x 16B = 9 * 256 threads
        asm volatile("cp.async.ca.shared.global [%0], [%1], 16;"
                     :: "r"(d + i * 4096), "l"(src + i * 4096) : "memory");
    }
    asm volatile("cp.async.commit_group;" ::: "memory");
}

__global__ void __launch_bounds__(BDIM, 1)
lstm_mma(const float* __restrict__ x,
         const float* __restrict__ linW,
         const float* __restrict__ linb,
         float* __restrict__ out)
{
    extern __shared__ char smem[];
    const uint32_t sb = smem_u32(smem);
    const int tid  = threadIdx.x;
    const int lane = tid & 31;
    const int w    = tid >> 5;
    const int mq   = w & 3;          // M quarter: rows mq*32..+31
    const int nh   = w >> 2;         // N half within 64-col chunk: cols nh*32..+31
    const int base_row = blockIdx.x * 128;

    // zero all smem (h=0, x pad lanes=0)
    {
        uint4 z = make_uint4(0, 0, 0, 0);
        uint4* p = (uint4*)smem;
        for (int i = tid; i < SMEM_TOTAL / 16; i += BDIM) p[i] = z;
    }
    __syncthreads();
    if (tid < 128) {    // bias lane k=133 = 1.0 (hi) in both buffers
        *(unsigned short*)(smem + 0 * ABUF + tid * ROWB + 266) = 0x3F80;
        *(unsigned short*)(smem + 2 * ABUF + tid * ROWB + 266) = 0x3F80;
    }

    float c_loc[64];
    #pragma unroll
    for (int i = 0; i < 64; i++) c_loc[i] = 0.f;

    cp_block(0, sb + SM_W, tid);
    __syncthreads();

    int cur = 0;
    for (int t = 0; t < 62; t++) {
        const int nb = cur ^ 1;

        // stage x(t) into k=128..132 of current buffer (t==49: both buffers,
        // providing ctx + last_velocity for the decoder's dec_in0)
        if (t < 50 && tid < 128) {
            const float* xp = x + (size_t)(base_row + tid) * 250 + (size_t)t * 5;
            float v[5] = { xp[0], xp[1], xp[2], xp[3], xp[4] };
            #pragma unroll
            for (int b = 0; b < 2; b++) {
                if (b == 1 && t != 49) break;
                int bsel = b == 0 ? cur : nb;
                char* bh = smem + bsel * 2 * ABUF + tid * ROWB + 256;  // k=128
                #pragma unroll
                for (int i = 0; i < 5; i++) {
                    unsigned short hu = bfu(v[i]);
                    *(unsigned short*)(bh + i * 2) = hu;
                    *(unsigned short*)(bh + ABUF + i * 2) = bfu(v[i] - ubf(hu));
                }
            }
        }

        for (int iter = 0; iter < 8; iter++) {
            const int lin = t * 8 + iter;
            // block lin was prefetched in the previous iter; ensure landed.
            asm volatile("cp.async.wait_group 0;" ::: "memory");
            __syncthreads();
            // prefetch next block; safe: barrier above separates all reads of
            // slot (lin+1)&1 for block lin-1 from these writes.
            {
                int nl = lin + 1; if (nl > NBLOCKS - 1) nl = NBLOCKS - 1;
                cp_block(nl, sb + SM_W + (uint32_t)(nl & 1) * WBLK, tid);
            }

            const uint32_t wb = sb + SM_W + (uint32_t)(lin & 1) * WBLK;
            const uint32_t ab = sb + (uint32_t)cur * 2 * ABUF;

            float acc[2][4][4];
            #pragma unroll
            for (int mt = 0; mt < 2; mt++)
                #pragma unroll
                for (int nt = 0; nt < 4; nt++)
                    #pragma unroll
                    for (int q = 0; q < 4; q++) acc[mt][nt][q] = 0.f;

            #pragma unroll
            for (int kt = 0; kt < 9; kt++) {
                uint32_t ah[2][4], al[2][4], bh_[2][4], bl_[2][4];
                const uint32_t kofA = (uint32_t)((kt * 16 + ((lane >> 4) << 3)) << 1);
                const uint32_t kofB = (uint32_t)((kt * 16 + (lane & 8)) << 1);
                #pragma unroll
                for (int mt = 0; mt < 2; mt++) {
                    uint32_t ra = ab + (uint32_t)(mq * 32 + mt * 16 + (lane & 15)) * ROWB + kofA;
                    LDSX4(ah[mt], ra);
                    LDSX4(al[mt], ra + ABUF);
                }
                #pragma unroll
                for (int p = 0; p < 2; p++) {
                    uint32_t rn = (uint32_t)(nh * 32 + p * 16 + ((lane >> 4) << 3)
                                  + (lane & 7)) * WROWB + kofB;
                    LDSX4(bh_[p], wb + rn);
                    LDSX4(bl_[p], wb + 18432 + rn);
                }
                // 3 sweeps over 8 independent tiles: dep distance 8
                #pragma unroll
                for (int mt = 0; mt < 2; mt++)
                    #pragma unroll
                    for (int nt = 0; nt < 4; nt++)
                        MMA16816(acc[mt][nt], ah[mt],
                                 bh_[nt >> 1][(nt & 1) * 2], bh_[nt >> 1][(nt & 1) * 2 + 1]);
                #pragma unroll
                for (int mt = 0; mt < 2; mt++)
                    #pragma unroll
                    for (int nt = 0; nt < 4; nt++)
                        MMA16816(acc[mt][nt], al[mt],
                                 bh_[nt >> 1][(nt & 1) * 2], bh_[nt >> 1][(nt & 1) * 2 + 1]);
                #pragma unroll
                for (int mt = 0; mt < 2; mt++)
                    #pragma unroll
                    for (int nt = 0; nt < 4; nt++)
                        MMA16816(acc[mt][nt], ah[mt],
                                 bl_[nt >> 1][(nt & 1) * 2], bl_[nt >> 1][(nt & 1) * 2 + 1]);
            }

            // epilogue: warp owns rows [mq*32..+31], units [iter*16+nh*8..+7]
            const int cb_u = iter * 16 + nh * 8;
            const bool even = !(lane & 1);
            #pragma unroll
            for (int mt = 0; mt < 2; mt++) {
                #pragma unroll
                for (int nt = 0; nt < 4; nt++) {
                    float c0 = acc[mt][nt][0], c1 = acc[mt][nt][1];
                    float c2 = acc[mt][nt][2], c3 = acc[mt][nt][3];
                    float x0 = __shfl_xor_sync(0xffffffffu, c0, 1);
                    float x1 = __shfl_xor_sync(0xffffffffu, c1, 1);
                    float x2 = __shfl_xor_sync(0xffffffffu, c2, 1);
                    float x3 = __shfl_xor_sync(0xffffffffu, c3, 1);
                    float iv = even ? c0 : x2;
                    float fv = even ? c1 : x3;
                    float gv = even ? x0 : c2;
                    float ov = even ? x1 : c3;
                    int row = mq * 32 + mt * 16 + (lane >> 2) + (even ? 0 : 8);
                    int ug  = cb_u + nt * 2 + ((lane & 3) >> 1);
                    int ci  = iter * 8 + mt * 4 + nt;
                    float ivs = sigf(iv), fvs = sigf(fv);
                    float gvt = tanhf_(gv), ovs = sigf(ov);
                    float cn = fmaf(fvs, c_loc[ci], ivs * gvt);
                    c_loc[ci] = cn;
                    float hv = ovs * tanhf_(cn);
                    unsigned short hu = bfu(hv);
                    char* bh = smem + nb * 2 * ABUF + row * ROWB + ug * 2;
                    *(unsigned short*)bh = hu;
                    *(unsigned short*)(bh + ABUF) = bfu(hv - ubf(hu));
                }
            }
        }

        if (t >= 50) {   // pred = h_new @ linW^T + linb; feed back velocity
            __syncthreads();   // all epilogue writes of this step visible
            int r = tid & 127, jj = tid >> 7;
            const char* bh = smem + nb * 2 * ABUF + r * ROWB;
            float accp = __ldg(linb + jj);
            const float* lw = linW + jj * 128;
            #pragma unroll 16
            for (int u = 0; u < 128; u++) {
                float hv = ubf(*(const unsigned short*)(bh + u * 2))
                         + ubf(*(const unsigned short*)(bh + ABUF + u * 2));
                accp = fmaf(hv, __ldg(lw + u), accp);
            }
            out[((size_t)(base_row + r) * 12 + (t - 50)) * 2 + jj] = accp;
            unsigned short hu = bfu(accp);
            char* bx = smem + nb * 2 * ABUF + r * ROWB + (128 + jj) * 2;
            *(unsigned short*)bx = hu;
            *(unsigned short*)(bx + ABUF) = bfu(accp - ubf(hu));
        }

        cur = nb;
    }
}

extern "C" void kernel_launch(void* const* d_in, const int* in_sizes, int n_in,
                              void* d_out, int out_size)
{
    const float* x    = (const float*)d_in[0];
    const float* eWih = (const float*)d_in[1];
    const float* eWhh = (const float*)d_in[2];
    const float* ebih = (const float*)d_in[3];
    const float* ebhh = (const float*)d_in[4];
    const float* dWih = (const float*)d_in[5];
    const float* dWhh = (const float*)d_in[6];
    const float* dbih = (const float*)d_in[7];
    const float* dbhh = (const float*)d_in[8];
    const float* lW   = (const float*)d_in[9];
    const float* lb   = (const float*)d_in[10];
    float* out = (float*)d_out;

    cudaFuncSetAttribute(lstm_mma, cudaFuncAttributeMaxDynamicSharedMemorySize, SMEM_TOTAL);

    prep_kernel<<<(16 * 18432 + 255) / 256, 256>>>(eWih, eWhh, ebih, ebhh,
                                                   dWih, dWhh, dbih, dbhh);
    lstm_mma<<<128, BDIM, SMEM_TOTAL>>>(x, lW, lb, out);
}